// round 1
// baseline (speedup 1.0000x reference)
#include <cuda_runtime.h>
#include <math.h>

#define BB 64
#define TT 384
#define DD 512
#define NDIAG (2 * TT - 1)   // 767

// Scratch (static __device__ arrays — no allocation allowed in kernel_launch)
__device__ float g_cost[BB][NDIAG][TT];   // cost matrix, DIAGONAL-major: [b][i+j][j]
__device__ float g_norm_a[BB * TT];       // ||pred_row||^2
__device__ float g_norm_b[BB * TT];       // ||targ_row||^2
__device__ float g_dist[BB];              // per-batch DTW distance

// ---------------------------------------------------------------------------
// Stage 0: row norms. One warp per row, float4 loads, warp reduction.
// rows = 2*B*T = 49152
// ---------------------------------------------------------------------------
__global__ void norms_kernel(const float* __restrict__ pred,
                             const float* __restrict__ targ) {
    int warp = (blockIdx.x * blockDim.x + threadIdx.x) >> 5;
    int lane = threadIdx.x & 31;
    int total = 2 * BB * TT;
    if (warp >= total) return;

    const float* base = (warp < BB * TT) ? (pred + (size_t)warp * DD)
                                         : (targ + (size_t)(warp - BB * TT) * DD);
    const float4* p4 = (const float4*)base;
    float s = 0.f;
#pragma unroll
    for (int k = 0; k < DD / 4 / 32; k++) {
        float4 v = p4[lane + k * 32];
        s += v.x * v.x + v.y * v.y + v.z * v.z + v.w * v.w;
    }
#pragma unroll
    for (int o = 16; o > 0; o >>= 1) s += __shfl_xor_sync(0xffffffffu, s, o);
    if (lane == 0) {
        if (warp < BB * TT) g_norm_a[warp] = s;
        else                g_norm_b[warp - BB * TT] = s;
    }
}

// ---------------------------------------------------------------------------
// Stage 1: batched "GEMM" dot = A @ B^T, epilogue sqrt(max(na+nb-2dot,0)),
// stored diagonal-major. Block = 64x64 tile of one batch, 256 threads,
// 4x4 register tile per thread, BK=16, transposed smem for LDS.128.
// ---------------------------------------------------------------------------
__global__ __launch_bounds__(256) void cost_kernel(const float* __restrict__ pred,
                                                   const float* __restrict__ targ) {
    __shared__ float As[16][68];   // [k][i], padded to soften store conflicts
    __shared__ float Bs[16][68];   // [k][j]

    const int b  = blockIdx.z;
    const int i0 = blockIdx.y * 64;
    const int j0 = blockIdx.x * 64;
    const float* A  = pred + (size_t)b * TT * DD;
    const float* Bm = targ + (size_t)b * TT * DD;

    const int tid  = threadIdx.x;
    const int tx   = tid & 15;        // j-group
    const int ty   = tid >> 4;        // i-group
    const int lrow = tid >> 2;        // 0..63 load row
    const int lk4  = (tid & 3) * 4;   // 0,4,8,12

    float acc[4][4];
#pragma unroll
    for (int m = 0; m < 4; m++)
#pragma unroll
        for (int n = 0; n < 4; n++) acc[m][n] = 0.f;

    for (int k0 = 0; k0 < DD; k0 += 16) {
        float4 av = *(const float4*)(A  + (size_t)(i0 + lrow) * DD + k0 + lk4);
        float4 bv = *(const float4*)(Bm + (size_t)(j0 + lrow) * DD + k0 + lk4);
        __syncthreads();   // previous iteration's reads complete
        As[lk4 + 0][lrow] = av.x; As[lk4 + 1][lrow] = av.y;
        As[lk4 + 2][lrow] = av.z; As[lk4 + 3][lrow] = av.w;
        Bs[lk4 + 0][lrow] = bv.x; Bs[lk4 + 1][lrow] = bv.y;
        Bs[lk4 + 2][lrow] = bv.z; Bs[lk4 + 3][lrow] = bv.w;
        __syncthreads();
#pragma unroll
        for (int kk = 0; kk < 16; kk++) {
            float4 a4 = *(const float4*)&As[kk][ty * 4];
            float4 b4 = *(const float4*)&Bs[kk][tx * 4];
            float am[4] = {a4.x, a4.y, a4.z, a4.w};
            float bn[4] = {b4.x, b4.y, b4.z, b4.w};
#pragma unroll
            for (int m = 0; m < 4; m++)
#pragma unroll
                for (int n = 0; n < 4; n++) acc[m][n] = fmaf(am[m], bn[n], acc[m][n]);
        }
    }

    float na[4], nb[4];
#pragma unroll
    for (int m = 0; m < 4; m++) na[m] = g_norm_a[b * TT + i0 + ty * 4 + m];
#pragma unroll
    for (int n = 0; n < 4; n++) nb[n] = g_norm_b[b * TT + j0 + tx * 4 + n];

#pragma unroll
    for (int m = 0; m < 4; m++) {
        int i = i0 + ty * 4 + m;
#pragma unroll
        for (int n = 0; n < 4; n++) {
            int j = j0 + tx * 4 + n;
            float sq = na[m] + nb[n] - 2.f * acc[m][n];
            g_cost[b][i + j][j] = sqrtf(fmaxf(sq, 0.f));
        }
    }
}

// ---------------------------------------------------------------------------
// Stage 2: DTW wavefront. One CTA per batch, thread j owns column j.
// D[i][j] = cost[i][j] + min(D[i-1][j], D[i][j-1], D[i-1][j-1]),
// virtual D[-1][-1]=0 borders INF (matches reference DP exactly).
// Diagonal-major cost => coalesced loads; depth-2 prefetch hides L2/HBM.
// ---------------------------------------------------------------------------
__global__ __launch_bounds__(TT) void dtw_kernel() {
    const int b = blockIdx.x;
    const int j = threadIdx.x;                 // 0..383
    __shared__ float buf[3][TT + 1];

    float* prev2 = buf[0];
    float* prev  = buf[1];
    float* cur   = buf[2];

    const float INF = INFINITY;
    buf[0][j + 1] = INF;
    buf[1][j + 1] = INF;
    if (j == 0) { buf[0][0] = INF; buf[1][0] = INF; buf[2][0] = INF; }
    __syncthreads();

    const float* costb = &g_cost[b][0][0];

    // active(d): j <= d  &&  j >= d - (T-1)
    auto ldc = [&](int d) -> float {
        if (d < NDIAG && j <= d && j >= d - (TT - 1)) return costb[d * TT + j];
        return 0.f;
    };

    float c0 = ldc(0);
    float c1 = ldc(1);

    for (int d = 0; d < NDIAG; d++) {
        float cn = ldc(d + 2);                         // prefetch 2 ahead
        bool active = (j <= d) && (j >= d - (TT - 1));
        float val = INF;
        if (active) {
            float up   = prev[j + 1];    // (i-1, j)
            float left = prev[j];        // (i,   j-1)
            float ul   = prev2[j];       // (i-1, j-1)
            float m3 = fminf(fminf(up, left), ul);
            val = (d == 0) ? c0 : (c0 + m3);
        }
        cur[j + 1] = val;                              // inactive -> INF
        __syncthreads();
        float* t = prev2; prev2 = prev; prev = cur; cur = t;
        c0 = c1; c1 = cn;
    }
    // after final rotation, prev holds diagonal 766; answer at column 383
    if (j == TT - 1) g_dist[b] = prev[TT];
}

// ---------------------------------------------------------------------------
// Stage 3: mean over 64 batch distances.
// ---------------------------------------------------------------------------
__global__ void reduce_kernel(float* __restrict__ out) {
    int lane = threadIdx.x;
    float s = g_dist[lane] + g_dist[lane + 32];
#pragma unroll
    for (int o = 16; o > 0; o >>= 1) s += __shfl_xor_sync(0xffffffffu, s, o);
    if (lane == 0) out[0] = s * (1.f / BB);
}

// ---------------------------------------------------------------------------
extern "C" void kernel_launch(void* const* d_in, const int* in_sizes, int n_in,
                              void* d_out, int out_size) {
    const float* pred = (const float*)d_in[0];
    const float* targ = (const float*)d_in[1];
    float* out = (float*)d_out;

    // norms: 2*B*T warps = 49152, 8 warps/block -> 6144 blocks
    norms_kernel<<<(2 * BB * TT) / 8, 256>>>(pred, targ);
    cost_kernel<<<dim3(TT / 64, TT / 64, BB), 256>>>(pred, targ);
    dtw_kernel<<<BB, TT>>>();
    reduce_kernel<<<1, 32>>>(out);
}

// round 4
// speedup vs baseline: 1.0842x; 1.0842x over previous
#include <cuda_runtime.h>
#include <math.h>
#include <cstdint>

#define BB 64
#define TT 384
#define DD 512

typedef unsigned long long ull;

// ---------------------------------------------------------------------------
// Device scratch (no allocation allowed anywhere)
// ---------------------------------------------------------------------------
__device__ float g_cost[BB][TT][TT];   // ROW-major cost matrix
__device__ float g_norm_a[BB * TT];
__device__ float g_norm_b[BB * TT];
__device__ float g_dist[BB];

// ---------------------------------------------------------------------------
// Packed f32x2 helpers (Blackwell, PTX ISA 8.6, sm_100+)
// ---------------------------------------------------------------------------
__device__ __forceinline__ void ffma2(ull& d, ull a, ull b) {
    asm("fma.rn.f32x2 %0, %1, %2, %0;" : "+l"(d) : "l"(a), "l"(b));
}
__device__ __forceinline__ ull dup2(float x) {
    ull d;
    asm("mov.b64 %0, {%1, %1};" : "=l"(d) : "r"(__float_as_uint(x)));
    return d;
}
__device__ __forceinline__ ull pack2(float x, float y) {
    ull d;
    asm("mov.b64 %0, {%1, %2};" : "=l"(d) : "r"(__float_as_uint(x)), "r"(__float_as_uint(y)));
    return d;
}
__device__ __forceinline__ void unpack2(ull v, float& lo, float& hi) {
    asm("mov.b64 {%0, %1}, %2;" : "=f"(lo), "=f"(hi) : "l"(v));
}

// ---------------------------------------------------------------------------
// Stage 0: row norms (one warp per row)
// ---------------------------------------------------------------------------
__global__ void norms_kernel(const float* __restrict__ pred,
                             const float* __restrict__ targ) {
    int warp = (blockIdx.x * blockDim.x + threadIdx.x) >> 5;
    int lane = threadIdx.x & 31;
    if (warp >= 2 * BB * TT) return;
    const float* base = (warp < BB * TT) ? (pred + (size_t)warp * DD)
                                         : (targ + (size_t)(warp - BB * TT) * DD);
    const float4* p4 = (const float4*)base;
    float s = 0.f;
#pragma unroll
    for (int k = 0; k < DD / 128; k++) {
        float4 v = p4[lane + k * 32];
        s += v.x * v.x + v.y * v.y + v.z * v.z + v.w * v.w;
    }
#pragma unroll
    for (int o = 16; o > 0; o >>= 1) s += __shfl_xor_sync(0xffffffffu, s, o);
    if (lane == 0) {
        if (warp < BB * TT) g_norm_a[warp] = s;
        else                g_norm_b[warp - BB * TT] = s;
    }
}

// ---------------------------------------------------------------------------
// Stage 1: cost GEMM, fp32 with packed f32x2 FMA.
// 128x128 tile per CTA, 256 threads, 8x8 per thread, BK=16 double-buffered.
// SMEM tiles transposed [k][row] so compute does broadcast LDS.128.
// ---------------------------------------------------------------------------
__global__ __launch_bounds__(256)
void cost_simt_kernel(const float* __restrict__ pred, const float* __restrict__ targ) {
    __shared__ float As[2][16][128];
    __shared__ float Bs[2][16][128];
    __shared__ float s_na[128], s_nb[128];

    const int b  = blockIdx.z;
    const int i0 = blockIdx.y * 128;
    const int j0 = blockIdx.x * 128;
    const int tid = threadIdx.x;
    const int tx  = tid & 15;         // col group (8 cols)
    const int ty  = tid >> 4;         // row group (8 rows)
    const int lrow = tid & 127;       // load row
    const int lk   = (tid >> 7) * 8;  // 0 or 8

    if (tid < 128) s_na[tid]       = g_norm_a[b * TT + i0 + tid];
    else           s_nb[tid - 128] = g_norm_b[b * TT + j0 + (tid - 128)];

    const float* Ag = pred + (size_t)b * TT * DD + (size_t)(i0 + lrow) * DD + lk;
    const float* Bg = targ + (size_t)b * TT * DD + (size_t)(j0 + lrow) * DD + lk;

    // prologue: chunk 0 -> buffer 0
    {
        float4 a0 = *(const float4*)(Ag);
        float4 a1 = *(const float4*)(Ag + 4);
        float4 b0 = *(const float4*)(Bg);
        float4 b1 = *(const float4*)(Bg + 4);
        As[0][lk + 0][lrow] = a0.x; As[0][lk + 1][lrow] = a0.y;
        As[0][lk + 2][lrow] = a0.z; As[0][lk + 3][lrow] = a0.w;
        As[0][lk + 4][lrow] = a1.x; As[0][lk + 5][lrow] = a1.y;
        As[0][lk + 6][lrow] = a1.z; As[0][lk + 7][lrow] = a1.w;
        Bs[0][lk + 0][lrow] = b0.x; Bs[0][lk + 1][lrow] = b0.y;
        Bs[0][lk + 2][lrow] = b0.z; Bs[0][lk + 3][lrow] = b0.w;
        Bs[0][lk + 4][lrow] = b1.x; Bs[0][lk + 5][lrow] = b1.y;
        Bs[0][lk + 6][lrow] = b1.z; Bs[0][lk + 7][lrow] = b1.w;
    }
    __syncthreads();

    ull acc[8][4];
#pragma unroll
    for (int m = 0; m < 8; m++)
#pragma unroll
        for (int np = 0; np < 4; np++) acc[m][np] = 0ull;

    for (int c = 0; c < DD / 16; c++) {          // 32 chunks
        const int cur = c & 1;
        float4 sa0, sa1, sb0, sb1;
        if (c < 31) {                            // stage next chunk in regs
            const float* ag = Ag + (c + 1) * 16;
            const float* bg = Bg + (c + 1) * 16;
            sa0 = *(const float4*)(ag);
            sa1 = *(const float4*)(ag + 4);
            sb0 = *(const float4*)(bg);
            sb1 = *(const float4*)(bg + 4);
        }
#pragma unroll
        for (int kk = 0; kk < 16; kk++) {
            float4 al = *(const float4*)&As[cur][kk][ty * 8];
            float4 ah = *(const float4*)&As[cur][kk][ty * 8 + 4];
            float4 bl = *(const float4*)&Bs[cur][kk][tx * 8];
            float4 bh = *(const float4*)&Bs[cur][kk][tx * 8 + 4];
            ull b2[4];
            b2[0] = pack2(bl.x, bl.y); b2[1] = pack2(bl.z, bl.w);
            b2[2] = pack2(bh.x, bh.y); b2[3] = pack2(bh.z, bh.w);
            ull a2[8];
            a2[0] = dup2(al.x); a2[1] = dup2(al.y); a2[2] = dup2(al.z); a2[3] = dup2(al.w);
            a2[4] = dup2(ah.x); a2[5] = dup2(ah.y); a2[6] = dup2(ah.z); a2[7] = dup2(ah.w);
#pragma unroll
            for (int m = 0; m < 8; m++)
#pragma unroll
                for (int np = 0; np < 4; np++) ffma2(acc[m][np], a2[m], b2[np]);
        }
        if (c < 31) {
            const int nxt = cur ^ 1;
            As[nxt][lk + 0][lrow] = sa0.x; As[nxt][lk + 1][lrow] = sa0.y;
            As[nxt][lk + 2][lrow] = sa0.z; As[nxt][lk + 3][lrow] = sa0.w;
            As[nxt][lk + 4][lrow] = sa1.x; As[nxt][lk + 5][lrow] = sa1.y;
            As[nxt][lk + 6][lrow] = sa1.z; As[nxt][lk + 7][lrow] = sa1.w;
            Bs[nxt][lk + 0][lrow] = sb0.x; Bs[nxt][lk + 1][lrow] = sb0.y;
            Bs[nxt][lk + 2][lrow] = sb0.z; Bs[nxt][lk + 3][lrow] = sb0.w;
            Bs[nxt][lk + 4][lrow] = sb1.x; Bs[nxt][lk + 5][lrow] = sb1.y;
            Bs[nxt][lk + 6][lrow] = sb1.z; Bs[nxt][lk + 7][lrow] = sb1.w;
            __syncthreads();
        }
    }

    // epilogue: cost = sqrt(max(na + nb - 2*dot, 0)), row-major coalesced stores
    float nb[8];
#pragma unroll
    for (int n = 0; n < 8; n++) nb[n] = s_nb[tx * 8 + n];
#pragma unroll
    for (int m = 0; m < 8; m++) {
        float na = s_na[ty * 8 + m];
        float r[8];
#pragma unroll
        for (int np = 0; np < 4; np++) unpack2(acc[m][np], r[2 * np], r[2 * np + 1]);
        float4 o0, o1;
        o0.x = sqrtf(fmaxf(na + nb[0] - 2.f * r[0], 0.f));
        o0.y = sqrtf(fmaxf(na + nb[1] - 2.f * r[1], 0.f));
        o0.z = sqrtf(fmaxf(na + nb[2] - 2.f * r[2], 0.f));
        o0.w = sqrtf(fmaxf(na + nb[3] - 2.f * r[3], 0.f));
        o1.x = sqrtf(fmaxf(na + nb[4] - 2.f * r[4], 0.f));
        o1.y = sqrtf(fmaxf(na + nb[5] - 2.f * r[5], 0.f));
        o1.z = sqrtf(fmaxf(na + nb[6] - 2.f * r[6], 0.f));
        o1.w = sqrtf(fmaxf(na + nb[7] - 2.f * r[7], 0.f));
        float* dst = &g_cost[b][i0 + ty * 8 + m][j0 + tx * 8];
        *(float4*)(dst)     = o0;
        *(float4*)(dst + 4) = o1;
    }
}

// ---------------------------------------------------------------------------
// Stage 2: DTW, one warp per batch, skewed lane pipeline, no barriers.
// Lane l owns cols [12l, 12l+12); row chunks of 8; 79 fixed steps (hang-free).
// ---------------------------------------------------------------------------
__global__ __launch_bounds__(32) void dtw_kernel() {
    const int b = blockIdx.x;
    const int lane = threadIdx.x;
    const float INF = __int_as_float(0x7f800000);
    const float* __restrict__ cb = &g_cost[b][0][0];

    float t[12], right[8], cornerSave = INF;
#pragma unroll
    for (int j = 0; j < 12; j++) t[j] = INF;
#pragma unroll
    for (int i = 0; i < 8; i++) right[i] = INF;

    for (int s = 0; s < 79; s++) {
        float lv[8];
#pragma unroll
        for (int i = 0; i < 8; i++) lv[i] = __shfl_up_sync(0xffffffffu, right[i], 1);
        float cornerIn = __shfl_up_sync(0xffffffffu, cornerSave, 1);
        cornerSave = right[7];           // chunk r-1 bottom row, for neighbor next step
        int r = s - lane;
        if (lane == 0) {
#pragma unroll
            for (int i = 0; i < 8; i++) lv[i] = INF;
            cornerIn = (r == 0) ? 0.f : INF;
        }
        if (r >= 0 && r < TT / 8) {
            const float* rp = cb + (size_t)r * 8 * TT + lane * 12;
#pragma unroll
            for (int ii = 0; ii < 8; ii++) {
                const float4* p4 = (const float4*)(rp + (size_t)ii * TT);
                float4 q0 = p4[0], q1 = p4[1], q2 = p4[2];
                float cst[12] = {q0.x, q0.y, q0.z, q0.w, q1.x, q1.y, q1.z, q1.w,
                                 q2.x, q2.y, q2.z, q2.w};
                float dgl = (ii == 0) ? cornerIn : lv[ii - 1];  // D[i-1][j-1]
                float cl  = lv[ii];                              // D[i][j-1]
#pragma unroll
                for (int jj = 0; jj < 12; jj++) {
                    float up = t[jj];                            // D[i-1][j]
                    float v  = cst[jj] + fminf(fminf(up, cl), dgl);
                    dgl = up;
                    t[jj] = v;
                    cl = v;
                }
                right[ii] = cl;
            }
        }
    }
    if (lane == 31) g_dist[b] = right[7];
}

// ---------------------------------------------------------------------------
// Stage 3: mean over batches
// ---------------------------------------------------------------------------
__global__ void reduce_kernel(float* __restrict__ out) {
    int lane = threadIdx.x;
    float s = g_dist[lane] + g_dist[lane + 32];
#pragma unroll
    for (int o = 16; o > 0; o >>= 1) s += __shfl_xor_sync(0xffffffffu, s, o);
    if (lane == 0) out[0] = s * (1.f / BB);
}

// ---------------------------------------------------------------------------
extern "C" void kernel_launch(void* const* d_in, const int* in_sizes, int n_in,
                              void* d_out, int out_size) {
    const float* pred = (const float*)d_in[0];
    const float* targ = (const float*)d_in[1];
    float* out = (float*)d_out;

    norms_kernel<<<(2 * BB * TT) / 8, 256>>>(pred, targ);
    cost_simt_kernel<<<dim3(TT / 128, TT / 128, BB), 256>>>(pred, targ);
    dtw_kernel<<<BB, 32>>>();
    reduce_kernel<<<1, 32>>>(out);
}

// round 7
// speedup vs baseline: 1.5443x; 1.4244x over previous
#include <cuda_runtime.h>
#include <cuda_bf16.h>
#include <math.h>
#include <cstdint>

#define BB 64
#define TT 384
#define DD 512

// ---------------------------------------------------------------------------
// Device scratch (no allocation allowed anywhere)
// ---------------------------------------------------------------------------
__device__ float g_cost[BB][TT][TT];   // ROW-major cost matrix
__device__ float g_norm_a[BB * TT];
__device__ float g_norm_b[BB * TT];
__device__ float g_dist[BB];

__device__ __forceinline__ uint32_t smem_u32(const void* p) {
    uint32_t a;
    asm("{ .reg .u64 t; cvta.to.shared.u64 t, %1; cvt.u32.u64 %0, t; }" : "=r"(a) : "l"(p));
    return a;
}
__device__ __forceinline__ uint32_t pack_bf16(float x, float y) {
    __nv_bfloat162 h = __floats2bfloat162_rn(x, y);
    return *reinterpret_cast<uint32_t*>(&h);
}
#define SWZ128(off) ((off) ^ (((off) >> 3) & 0x70))

__device__ __forceinline__ void ldmatrix_x4(uint32_t& r0, uint32_t& r1,
                                            uint32_t& r2, uint32_t& r3, uint32_t addr) {
    asm volatile("ldmatrix.sync.aligned.m8n8.x4.shared.b16 {%0,%1,%2,%3}, [%4];"
                 : "=r"(r0), "=r"(r1), "=r"(r2), "=r"(r3) : "r"(addr));
}
__device__ __forceinline__ void mma_bf16(float* c, const uint32_t* a, const uint32_t* b) {
    asm volatile("mma.sync.aligned.m16n8k16.row.col.f32.bf16.bf16.f32 "
                 "{%0,%1,%2,%3}, {%4,%5,%6,%7}, {%8,%9}, {%0,%1,%2,%3};"
                 : "+f"(c[0]), "+f"(c[1]), "+f"(c[2]), "+f"(c[3])
                 : "r"(a[0]), "r"(a[1]), "r"(a[2]), "r"(a[3]), "r"(b[0]), "r"(b[1]));
}

// ---------------------------------------------------------------------------
// Stage 0: row norms (one warp per row) — unchanged from passing R4
// ---------------------------------------------------------------------------
__global__ void norms_kernel(const float* __restrict__ pred,
                             const float* __restrict__ targ) {
    int warp = (blockIdx.x * blockDim.x + threadIdx.x) >> 5;
    int lane = threadIdx.x & 31;
    if (warp >= 2 * BB * TT) return;
    const float* base = (warp < BB * TT) ? (pred + (size_t)warp * DD)
                                         : (targ + (size_t)(warp - BB * TT) * DD);
    const float4* p4 = (const float4*)base;
    float s = 0.f;
#pragma unroll
    for (int k = 0; k < DD / 128; k++) {
        float4 v = p4[lane + k * 32];
        s += v.x * v.x + v.y * v.y + v.z * v.z + v.w * v.w;
    }
#pragma unroll
    for (int o = 16; o > 0; o >>= 1) s += __shfl_xor_sync(0xffffffffu, s, o);
    if (lane == 0) {
        if (warp < BB * TT) g_norm_a[warp] = s;
        else                g_norm_b[warp - BB * TT] = s;
    }
}

// ---------------------------------------------------------------------------
// Stage 1: cost GEMM via warp-level bf16 HMMA (mma.sync m16n8k16, sm_80+ path,
// legal on compute_100). 128x128 tile/CTA, 8 warps (2m x 4n), warp tile 64x32,
// BK=64 bf16 (128B SW128 rows). Single SMEM buffer, next chunk staged in regs
// in two halves (reduced live-register peak). fp32->bf16 fused in SMEM stores.
// ---------------------------------------------------------------------------
__global__ __launch_bounds__(256)
void cost_hmma_kernel(const float* __restrict__ pred, const float* __restrict__ targ) {
    __shared__ __align__(1024) unsigned char sA[128 * 128];  // 128 rows x 64 bf16
    __shared__ __align__(1024) unsigned char sB[128 * 128];
    __shared__ float s_na[128], s_nb[128];

    const int b  = blockIdx.z;
    const int i0 = blockIdx.y * 128;
    const int j0 = blockIdx.x * 128;
    const int tid  = threadIdx.x;
    const int wid  = tid >> 5;
    const int lane = tid & 31;
    const int moff = (wid >> 2) * 64;   // warp m offset (0,64)
    const int noff = (wid & 3) * 32;    // warp n offset (0,32,64,96)

    const uint32_t sAb = smem_u32(sA);
    const uint32_t sBb = smem_u32(sB);

    if (tid < 128) s_na[tid]       = g_norm_a[b * TT + i0 + tid];
    else           s_nb[tid - 128] = g_norm_b[b * TT + j0 + (tid - 128)];

    // global->smem mapping: thread handles (row = tid>>1, 32-col half = tid&1)
    const int lrow = tid >> 1;
    const int half = tid & 1;
    const float* Ag = pred + (size_t)b * TT * DD + (size_t)(i0 + lrow) * DD + half * 32;
    const float* Bg = targ + (size_t)b * TT * DD + (size_t)(j0 + lrow) * DD + half * 32;
    const uint32_t dst = (uint32_t)lrow * 128 + half * 64;

    // ldmatrix lane-address components
    const int quad = lane >> 3;         // which 8x8 matrix this lane addresses
    const int r8   = lane & 7;
    // A: matrices (m0-7,k0-7),(m8-15,k0-7),(m0-7,k8-15),(m8-15,k8-15)
    const int a_mrow_base = moff + (quad & 1) * 8 + r8;
    const int a_kb_base   = (quad >> 1) * 16;
    // B: matrices (n0-7,k0-7),(n0-7,k8-15),(n8-15,k0-7),(n8-15,k8-15)
    const int b_nrow_base = noff + (quad >> 1) * 8 + r8;
    const int b_kb_base   = (quad & 1) * 16;

    float acc[4][4][4];                  // [mi][ni][reg]
#pragma unroll
    for (int mi = 0; mi < 4; mi++)
#pragma unroll
        for (int ni = 0; ni < 4; ni++)
#pragma unroll
            for (int r = 0; r < 4; r++) acc[mi][ni][r] = 0.f;

    // helper lambdas keep staging code compact (inlined by compiler)
    auto store_quarter = [&](const float4& a0, const float4& a1,
                             const float4& b0, const float4& b1, int p) {
        uint4 pa, pb;
        pa.x = pack_bf16(a0.x, a0.y); pa.y = pack_bf16(a0.z, a0.w);
        pa.z = pack_bf16(a1.x, a1.y); pa.w = pack_bf16(a1.z, a1.w);
        pb.x = pack_bf16(b0.x, b0.y); pb.y = pack_bf16(b0.z, b0.w);
        pb.z = pack_bf16(b1.x, b1.y); pb.w = pack_bf16(b1.z, b1.w);
        uint32_t o = SWZ128(dst + p * 16);
        *(uint4*)(sA + o) = pa;
        *(uint4*)(sB + o) = pb;
    };

    // preload chunk 0 (half at a time to limit live registers)
    float4 av[4], bv[4];
#pragma unroll
    for (int q = 0; q < 4; q++) { av[q] = ((const float4*)Ag)[q]; bv[q] = ((const float4*)Bg)[q]; }

    for (int c = 0; c < 8; c++) {        // 8 chunks of BK=64
        // first half of chunk c -> SMEM
        store_quarter(av[0], av[1], bv[0], bv[1], 0);
        store_quarter(av[2], av[3], bv[2], bv[3], 1);
        // second half of chunk c: load + store
#pragma unroll
        for (int q = 0; q < 4; q++) {
            av[q] = ((const float4*)(Ag + c * 64))[q + 4];
            bv[q] = ((const float4*)(Bg + c * 64))[q + 4];
        }
        store_quarter(av[0], av[1], bv[0], bv[1], 2);
        store_quarter(av[2], av[3], bv[2], bv[3], 3);
        __syncthreads();

        if (c < 7) {                     // stage first half of next chunk (overlaps MMA)
#pragma unroll
            for (int q = 0; q < 4; q++) {
                av[q] = ((const float4*)(Ag + (c + 1) * 64))[q];
                bv[q] = ((const float4*)(Bg + (c + 1) * 64))[q];
            }
        }

#pragma unroll
        for (int ks = 0; ks < 4; ks++) { // 4 k-steps of 16 within the chunk
            uint32_t afr[4][4], bfr[2][4];
#pragma unroll
            for (int mi = 0; mi < 4; mi++) {
                uint32_t addr = sAb + SWZ128((uint32_t)(a_mrow_base + mi * 16) * 128
                                             + (uint32_t)(ks * 32 + a_kb_base));
                ldmatrix_x4(afr[mi][0], afr[mi][1], afr[mi][2], afr[mi][3], addr);
            }
#pragma unroll
            for (int np = 0; np < 2; np++) {
                uint32_t addr = sBb + SWZ128((uint32_t)(b_nrow_base + np * 16) * 128
                                             + (uint32_t)(ks * 32 + b_kb_base));
                ldmatrix_x4(bfr[np][0], bfr[np][1], bfr[np][2], bfr[np][3], addr);
            }
#pragma unroll
            for (int mi = 0; mi < 4; mi++)
#pragma unroll
                for (int ni = 0; ni < 4; ni++)
                    mma_bf16(acc[mi][ni], afr[mi], &bfr[ni >> 1][(ni & 1) * 2]);
        }
        __syncthreads();
    }

    // epilogue: cost = sqrt(max(na + nb - 2*dot, 0)) from accumulator fragments
    const int g  = lane >> 2;            // groupID -> row within 16-tile
    const int cp = (lane & 3) * 2;       // col pair within 8-tile
#pragma unroll
    for (int mi = 0; mi < 4; mi++) {
#pragma unroll
        for (int half_m = 0; half_m < 2; half_m++) {
            int mrow = moff + mi * 16 + half_m * 8 + g;
            float na = s_na[mrow];
            float* grow = &g_cost[b][i0 + mrow][j0];
#pragma unroll
            for (int ni = 0; ni < 4; ni++) {
                int ncol = noff + ni * 8 + cp;
                float d0 = acc[mi][ni][half_m * 2 + 0];
                float d1 = acc[mi][ni][half_m * 2 + 1];
                float2 o;
                o.x = sqrtf(fmaxf(na + s_nb[ncol]     - 2.f * d0, 0.f));
                o.y = sqrtf(fmaxf(na + s_nb[ncol + 1] - 2.f * d1, 0.f));
                *(float2*)(grow + ncol) = o;
            }
        }
    }
}

// ---------------------------------------------------------------------------
// Stage 2: DTW — unchanged from passing R4 (warp pipeline, 79 fixed steps)
// ---------------------------------------------------------------------------
__global__ __launch_bounds__(32) void dtw_kernel() {
    const int b = blockIdx.x;
    const int lane = threadIdx.x;
    const float INF = __int_as_float(0x7f800000);
    const float* __restrict__ cb = &g_cost[b][0][0];

    float t[12], right[8], cornerSave = INF;
#pragma unroll
    for (int j = 0; j < 12; j++) t[j] = INF;
#pragma unroll
    for (int i = 0; i < 8; i++) right[i] = INF;

    for (int s = 0; s < 79; s++) {
        float lv[8];
#pragma unroll
        for (int i = 0; i < 8; i++) lv[i] = __shfl_up_sync(0xffffffffu, right[i], 1);
        float cornerIn = __shfl_up_sync(0xffffffffu, cornerSave, 1);
        cornerSave = right[7];
        int r = s - lane;
        if (lane == 0) {
#pragma unroll
            for (int i = 0; i < 8; i++) lv[i] = INF;
            cornerIn = (r == 0) ? 0.f : INF;
        }
        if (r >= 0 && r < TT / 8) {
            const float* rp = cb + (size_t)r * 8 * TT + lane * 12;
#pragma unroll
            for (int ii = 0; ii < 8; ii++) {
                const float4* p4 = (const float4*)(rp + (size_t)ii * TT);
                float4 q0 = p4[0], q1 = p4[1], q2 = p4[2];
                float cst[12] = {q0.x, q0.y, q0.z, q0.w, q1.x, q1.y, q1.z, q1.w,
                                 q2.x, q2.y, q2.z, q2.w};
                float dgl = (ii == 0) ? cornerIn : lv[ii - 1];
                float cl  = lv[ii];
#pragma unroll
                for (int jj = 0; jj < 12; jj++) {
                    float up = t[jj];
                    float v  = cst[jj] + fminf(fminf(up, cl), dgl);
                    dgl = up;
                    t[jj] = v;
                    cl = v;
                }
                right[ii] = cl;
            }
        }
    }
    if (lane == 31) g_dist[b] = right[7];
}

// ---------------------------------------------------------------------------
// Stage 3: mean — unchanged
// ---------------------------------------------------------------------------
__global__ void reduce_kernel(float* __restrict__ out) {
    int lane = threadIdx.x;
    float s = g_dist[lane] + g_dist[lane + 32];
#pragma unroll
    for (int o = 16; o > 0; o >>= 1) s += __shfl_xor_sync(0xffffffffu, s, o);
    if (lane == 0) out[0] = s * (1.f / BB);
}

// ---------------------------------------------------------------------------
extern "C" void kernel_launch(void* const* d_in, const int* in_sizes, int n_in,
                              void* d_out, int out_size) {
    const float* pred = (const float*)d_in[0];
    const float* targ = (const float*)d_in[1];
    float* out = (float*)d_out;

    norms_kernel<<<(2 * BB * TT) / 8, 256>>>(pred, targ);
    cost_hmma_kernel<<<dim3(TT / 128, TT / 128, BB), 256>>>(pred, targ);
    dtw_kernel<<<BB, 32>>>();
    reduce_kernel<<<1, 32>>>(out);
}

// round 10
// speedup vs baseline: 1.5603x; 1.0103x over previous
#include <cuda_runtime.h>
#include <cuda_bf16.h>
#include <math.h>
#include <cstdint>

#define BB 64
#define TT 384
#define DD 512

// ---------------------------------------------------------------------------
// Device scratch (no allocation allowed anywhere)
// ---------------------------------------------------------------------------
__device__ float g_cost[BB][TT][TT];   // ROW-major cost matrix
__device__ float g_dist[BB];

__device__ __forceinline__ uint32_t smem_u32(const void* p) {
    uint32_t a;
    asm("{ .reg .u64 t; cvta.to.shared.u64 t, %1; cvt.u32.u64 %0, t; }" : "=r"(a) : "l"(p));
    return a;
}
__device__ __forceinline__ uint32_t pack_bf16(float x, float y) {
    __nv_bfloat162 h = __floats2bfloat162_rn(x, y);
    return *reinterpret_cast<uint32_t*>(&h);
}
#define SWZ128(off) ((off) ^ (((off) >> 3) & 0x70))

__device__ __forceinline__ void ldmatrix_x4(uint32_t& r0, uint32_t& r1,
                                            uint32_t& r2, uint32_t& r3, uint32_t addr) {
    asm volatile("ldmatrix.sync.aligned.m8n8.x4.shared.b16 {%0,%1,%2,%3}, [%4];"
                 : "=r"(r0), "=r"(r1), "=r"(r2), "=r"(r3) : "r"(addr));
}
__device__ __forceinline__ void mma_bf16(float* c, const uint32_t* a, const uint32_t* b) {
    asm volatile("mma.sync.aligned.m16n8k16.row.col.f32.bf16.bf16.f32 "
                 "{%0,%1,%2,%3}, {%4,%5,%6,%7}, {%8,%9}, {%0,%1,%2,%3};"
                 : "+f"(c[0]), "+f"(c[1]), "+f"(c[2]), "+f"(c[3])
                 : "r"(a[0]), "r"(a[1]), "r"(a[2]), "r"(a[3]), "r"(b[0]), "r"(b[1]));
}

// ---------------------------------------------------------------------------
// Stage 1: bf16 HMMA cost GEMM (structure identical to the PASSING R7 kernel)
// with row norms fused in: each thread accumulates sum-of-squares of the fp32
// values it stages (covers half a row); pairs combine via smem.
// 128x128 tile/CTA, 8 warps (2m x 4n), BK=64 bf16 (128B SW128 rows).
// ---------------------------------------------------------------------------
__global__ __launch_bounds__(256)
void cost_hmma_kernel(const float* __restrict__ pred, const float* __restrict__ targ) {
    __shared__ __align__(1024) unsigned char sA[128 * 128];  // 128 rows x 64 bf16
    __shared__ __align__(1024) unsigned char sB[128 * 128];
    __shared__ float s_pna[128][2], s_pnb[128][2];           // per-half norm partials

    const int b  = blockIdx.z;
    const int i0 = blockIdx.y * 128;
    const int j0 = blockIdx.x * 128;
    const int tid  = threadIdx.x;
    const int wid  = tid >> 5;
    const int lane = tid & 31;
    const int moff = (wid >> 2) * 64;   // warp m offset (0,64)
    const int noff = (wid & 3) * 32;    // warp n offset (0,32,64,96)

    const uint32_t sAb = smem_u32(sA);
    const uint32_t sBb = smem_u32(sB);

    // global->smem mapping: thread handles (row = tid>>1, 32-col half = tid&1)
    const int lrow = tid >> 1;
    const int half = tid & 1;
    const float* Ag = pred + (size_t)b * TT * DD + (size_t)(i0 + lrow) * DD + half * 32;
    const float* Bg = targ + (size_t)b * TT * DD + (size_t)(j0 + lrow) * DD + half * 32;
    const uint32_t dst = (uint32_t)lrow * 128 + half * 64;

    // ldmatrix lane-address components
    const int quad = lane >> 3;
    const int r8   = lane & 7;
    const int a_mrow_base = moff + (quad & 1) * 8 + r8;
    const int a_kb_base   = (quad >> 1) * 16;
    const int b_nrow_base = noff + (quad >> 1) * 8 + r8;
    const int b_kb_base   = (quad & 1) * 16;

    float acc[4][4][4];                  // [mi][ni][reg]
#pragma unroll
    for (int mi = 0; mi < 4; mi++)
#pragma unroll
        for (int ni = 0; ni < 4; ni++)
#pragma unroll
            for (int r = 0; r < 4; r++) acc[mi][ni][r] = 0.f;

    float na_part = 0.f, nb_part = 0.f;  // fused norm partials

    auto accum_norm = [&](const float4* a, const float4* bq) {
#pragma unroll
        for (int q = 0; q < 4; q++) {
            na_part += a[q].x * a[q].x + a[q].y * a[q].y + a[q].z * a[q].z + a[q].w * a[q].w;
            nb_part += bq[q].x * bq[q].x + bq[q].y * bq[q].y + bq[q].z * bq[q].z + bq[q].w * bq[q].w;
        }
    };
    auto store_quarter = [&](const float4& a0, const float4& a1,
                             const float4& b0, const float4& b1, int p) {
        uint4 pa, pb;
        pa.x = pack_bf16(a0.x, a0.y); pa.y = pack_bf16(a0.z, a0.w);
        pa.z = pack_bf16(a1.x, a1.y); pa.w = pack_bf16(a1.z, a1.w);
        pb.x = pack_bf16(b0.x, b0.y); pb.y = pack_bf16(b0.z, b0.w);
        pb.z = pack_bf16(b1.x, b1.y); pb.w = pack_bf16(b1.z, b1.w);
        uint32_t o = SWZ128(dst + p * 16);
        *(uint4*)(sA + o) = pa;
        *(uint4*)(sB + o) = pb;
    };

    // preload chunk 0 first half
    float4 av[4], bv[4];
#pragma unroll
    for (int q = 0; q < 4; q++) { av[q] = ((const float4*)Ag)[q]; bv[q] = ((const float4*)Bg)[q]; }
    accum_norm(av, bv);

    for (int c = 0; c < 8; c++) {        // 8 chunks of BK=64
        store_quarter(av[0], av[1], bv[0], bv[1], 0);
        store_quarter(av[2], av[3], bv[2], bv[3], 1);
        // second half of chunk c
#pragma unroll
        for (int q = 0; q < 4; q++) {
            av[q] = ((const float4*)(Ag + c * 64))[q + 4];
            bv[q] = ((const float4*)(Bg + c * 64))[q + 4];
        }
        accum_norm(av, bv);
        store_quarter(av[0], av[1], bv[0], bv[1], 2);
        store_quarter(av[2], av[3], bv[2], bv[3], 3);
        __syncthreads();

        if (c < 7) {                     // first half of next chunk (overlaps MMAs)
#pragma unroll
            for (int q = 0; q < 4; q++) {
                av[q] = ((const float4*)(Ag + (c + 1) * 64))[q];
                bv[q] = ((const float4*)(Bg + (c + 1) * 64))[q];
            }
            accum_norm(av, bv);
        }

#pragma unroll
        for (int ks = 0; ks < 4; ks++) { // 4 k-steps of 16 within the chunk
            uint32_t afr[4][4], bfr[2][4];
#pragma unroll
            for (int mi = 0; mi < 4; mi++) {
                uint32_t addr = sAb + SWZ128((uint32_t)(a_mrow_base + mi * 16) * 128
                                             + (uint32_t)(ks * 32 + a_kb_base));
                ldmatrix_x4(afr[mi][0], afr[mi][1], afr[mi][2], afr[mi][3], addr);
            }
#pragma unroll
            for (int np = 0; np < 2; np++) {
                uint32_t addr = sBb + SWZ128((uint32_t)(b_nrow_base + np * 16) * 128
                                             + (uint32_t)(ks * 32 + b_kb_base));
                ldmatrix_x4(bfr[np][0], bfr[np][1], bfr[np][2], bfr[np][3], addr);
            }
#pragma unroll
            for (int mi = 0; mi < 4; mi++)
#pragma unroll
                for (int ni = 0; ni < 4; ni++)
                    mma_bf16(acc[mi][ni], afr[mi], &bfr[ni >> 1][(ni & 1) * 2]);
        }
        __syncthreads();
    }

    // publish norm partials (each thread staged exactly half of its row)
    s_pna[lrow][half] = na_part;
    s_pnb[lrow][half] = nb_part;
    __syncthreads();

    // epilogue: cost = sqrt(max(na + nb - 2*dot, 0)) from accumulator fragments
    const int g  = lane >> 2;            // row within 16-tile
    const int cp = (lane & 3) * 2;       // col pair within 8-tile
#pragma unroll
    for (int mi = 0; mi < 4; mi++) {
#pragma unroll
        for (int half_m = 0; half_m < 2; half_m++) {
            int mrow = moff + mi * 16 + half_m * 8 + g;
            float na = s_pna[mrow][0] + s_pna[mrow][1];
            float* grow = &g_cost[b][i0 + mrow][j0];
#pragma unroll
            for (int ni = 0; ni < 4; ni++) {
                int ncol = noff + ni * 8 + cp;
                float nb0 = s_pnb[ncol][0]     + s_pnb[ncol][1];
                float nb1 = s_pnb[ncol + 1][0] + s_pnb[ncol + 1][1];
                float d0 = acc[mi][ni][half_m * 2 + 0];
                float d1 = acc[mi][ni][half_m * 2 + 1];
                float2 o;
                o.x = sqrtf(fmaxf(na + nb0 - 2.f * d0, 0.f));
                o.y = sqrtf(fmaxf(na + nb1 - 2.f * d1, 0.f));
                *(float2*)(grow + ncol) = o;
            }
        }
    }
}

// ---------------------------------------------------------------------------
// Stage 2: DTW warp pipeline — reassociated recurrence (min(up,diag) computed
// off the serial chain; chain is fmin+add = 8 cyc/cell). 79 fixed steps.
// ---------------------------------------------------------------------------
__global__ __launch_bounds__(32) void dtw_kernel() {
    const int b = blockIdx.x;
    const int lane = threadIdx.x;
    const float INF = __int_as_float(0x7f800000);
    const float* __restrict__ cb = &g_cost[b][0][0];

    float t[12], right[8], cornerSave = INF;
#pragma unroll
    for (int j = 0; j < 12; j++) t[j] = INF;
#pragma unroll
    for (int i = 0; i < 8; i++) right[i] = INF;

    for (int s = 0; s < 79; s++) {
        float lv[8];
#pragma unroll
        for (int i = 0; i < 8; i++) lv[i] = __shfl_up_sync(0xffffffffu, right[i], 1);
        float cornerIn = __shfl_up_sync(0xffffffffu, cornerSave, 1);
        cornerSave = right[7];
        int r = s - lane;
        if (lane == 0) {
#pragma unroll
            for (int i = 0; i < 8; i++) lv[i] = INF;
            cornerIn = (r == 0) ? 0.f : INF;
        }
        if (r >= 0 && r < TT / 8) {
            const float* rp = cb + (size_t)r * 8 * TT + lane * 12;
#pragma unroll
            for (int ii = 0; ii < 8; ii++) {
                const float4* p4 = (const float4*)(rp + (size_t)ii * TT);
                float4 q0 = p4[0], q1 = p4[1], q2 = p4[2];
                float cst[12] = {q0.x, q0.y, q0.z, q0.w, q1.x, q1.y, q1.z, q1.w,
                                 q2.x, q2.y, q2.z, q2.w};
                // off-chain: m[jj] = min(up, diag) from previous-row values
                float m[12];
                m[0] = fminf(t[0], (ii == 0) ? cornerIn : lv[ii - 1]);
#pragma unroll
                for (int jj = 1; jj < 12; jj++) m[jj] = fminf(t[jj], t[jj - 1]);
                // serial chain: cl' = cst + min(m, cl)
                float cl = lv[ii];
#pragma unroll
                for (int jj = 0; jj < 12; jj++) {
                    float v = cst[jj] + fminf(m[jj], cl);
                    t[jj] = v;
                    cl = v;
                }
                right[ii] = cl;
            }
        }
    }
    if (lane == 31) g_dist[b] = right[7];
}

// ---------------------------------------------------------------------------
// Stage 3: mean — unchanged
// ---------------------------------------------------------------------------
__global__ void reduce_kernel(float* __restrict__ out) {
    int lane = threadIdx.x;
    float s = g_dist[lane] + g_dist[lane + 32];
#pragma unroll
    for (int o = 16; o > 0; o >>= 1) s += __shfl_xor_sync(0xffffffffu, s, o);
    if (lane == 0) out[0] = s * (1.f / BB);
}

// ---------------------------------------------------------------------------
extern "C" void kernel_launch(void* const* d_in, const int* in_sizes, int n_in,
                              void* d_out, int out_size) {
    const float* pred = (const float*)d_in[0];
    const float* targ = (const float*)d_in[1];
    float* out = (float*)d_out;

    cost_hmma_kernel<<<dim3(TT / 128, TT / 128, BB), 256>>>(pred, targ);
    dtw_kernel<<<BB, 32>>>();
    reduce_kernel<<<1, 32>>>(out);
}

// round 11
// speedup vs baseline: 2.1544x; 1.3808x over previous
#include <cuda_runtime.h>
#include <cuda_bf16.h>
#include <math.h>
#include <cstdint>

#define BB 64
#define TT 384
#define DD 512

// ---------------------------------------------------------------------------
// Device scratch (no allocation allowed anywhere)
// ---------------------------------------------------------------------------
__device__ float g_cost[BB][TT][TT];   // ROW-major cost matrix
__device__ float g_dist[BB];

__device__ __forceinline__ uint32_t smem_u32(const void* p) {
    uint32_t a;
    asm("{ .reg .u64 t; cvta.to.shared.u64 t, %1; cvt.u32.u64 %0, t; }" : "=r"(a) : "l"(p));
    return a;
}
__device__ __forceinline__ uint32_t pack_bf16(float x, float y) {
    __nv_bfloat162 h = __floats2bfloat162_rn(x, y);
    return *reinterpret_cast<uint32_t*>(&h);
}
#define SWZ128(off) ((off) ^ (((off) >> 3) & 0x70))

__device__ __forceinline__ void ldmatrix_x4(uint32_t& r0, uint32_t& r1,
                                            uint32_t& r2, uint32_t& r3, uint32_t addr) {
    asm volatile("ldmatrix.sync.aligned.m8n8.x4.shared.b16 {%0,%1,%2,%3}, [%4];"
                 : "=r"(r0), "=r"(r1), "=r"(r2), "=r"(r3) : "r"(addr));
}
__device__ __forceinline__ void mma_bf16(float* c, const uint32_t* a, const uint32_t* b) {
    asm volatile("mma.sync.aligned.m16n8k16.row.col.f32.bf16.bf16.f32 "
                 "{%0,%1,%2,%3}, {%4,%5,%6,%7}, {%8,%9}, {%0,%1,%2,%3};"
                 : "+f"(c[0]), "+f"(c[1]), "+f"(c[2]), "+f"(c[3])
                 : "r"(a[0]), "r"(a[1]), "r"(a[2]), "r"(a[3]), "r"(b[0]), "r"(b[1]));
}

// ---------------------------------------------------------------------------
// Stage 1: bf16 HMMA cost GEMM — BYTE-IDENTICAL to the passing R10 kernel.
// 128x128 tile/CTA, 8 warps (2m x 4n), BK=64, norms fused into staging.
// ---------------------------------------------------------------------------
__global__ __launch_bounds__(256)
void cost_hmma_kernel(const float* __restrict__ pred, const float* __restrict__ targ) {
    __shared__ __align__(1024) unsigned char sA[128 * 128];
    __shared__ __align__(1024) unsigned char sB[128 * 128];
    __shared__ float s_pna[128][2], s_pnb[128][2];

    const int b  = blockIdx.z;
    const int i0 = blockIdx.y * 128;
    const int j0 = blockIdx.x * 128;
    const int tid  = threadIdx.x;
    const int wid  = tid >> 5;
    const int lane = tid & 31;
    const int moff = (wid >> 2) * 64;
    const int noff = (wid & 3) * 32;

    const uint32_t sAb = smem_u32(sA);
    const uint32_t sBb = smem_u32(sB);

    const int lrow = tid >> 1;
    const int half = tid & 1;
    const float* Ag = pred + (size_t)b * TT * DD + (size_t)(i0 + lrow) * DD + half * 32;
    const float* Bg = targ + (size_t)b * TT * DD + (size_t)(j0 + lrow) * DD + half * 32;
    const uint32_t dst = (uint32_t)lrow * 128 + half * 64;

    const int quad = lane >> 3;
    const int r8   = lane & 7;
    const int a_mrow_base = moff + (quad & 1) * 8 + r8;
    const int a_kb_base   = (quad >> 1) * 16;
    const int b_nrow_base = noff + (quad >> 1) * 8 + r8;
    const int b_kb_base   = (quad & 1) * 16;

    float acc[4][4][4];
#pragma unroll
    for (int mi = 0; mi < 4; mi++)
#pragma unroll
        for (int ni = 0; ni < 4; ni++)
#pragma unroll
            for (int r = 0; r < 4; r++) acc[mi][ni][r] = 0.f;

    float na_part = 0.f, nb_part = 0.f;

    auto accum_norm = [&](const float4* a, const float4* bq) {
#pragma unroll
        for (int q = 0; q < 4; q++) {
            na_part += a[q].x * a[q].x + a[q].y * a[q].y + a[q].z * a[q].z + a[q].w * a[q].w;
            nb_part += bq[q].x * bq[q].x + bq[q].y * bq[q].y + bq[q].z * bq[q].z + bq[q].w * bq[q].w;
        }
    };
    auto store_quarter = [&](const float4& a0, const float4& a1,
                             const float4& b0, const float4& b1, int p) {
        uint4 pa, pb;
        pa.x = pack_bf16(a0.x, a0.y); pa.y = pack_bf16(a0.z, a0.w);
        pa.z = pack_bf16(a1.x, a1.y); pa.w = pack_bf16(a1.z, a1.w);
        pb.x = pack_bf16(b0.x, b0.y); pb.y = pack_bf16(b0.z, b0.w);
        pb.z = pack_bf16(b1.x, b1.y); pb.w = pack_bf16(b1.z, b1.w);
        uint32_t o = SWZ128(dst + p * 16);
        *(uint4*)(sA + o) = pa;
        *(uint4*)(sB + o) = pb;
    };

    float4 av[4], bv[4];
#pragma unroll
    for (int q = 0; q < 4; q++) { av[q] = ((const float4*)Ag)[q]; bv[q] = ((const float4*)Bg)[q]; }
    accum_norm(av, bv);

    for (int c = 0; c < 8; c++) {
        store_quarter(av[0], av[1], bv[0], bv[1], 0);
        store_quarter(av[2], av[3], bv[2], bv[3], 1);
#pragma unroll
        for (int q = 0; q < 4; q++) {
            av[q] = ((const float4*)(Ag + c * 64))[q + 4];
            bv[q] = ((const float4*)(Bg + c * 64))[q + 4];
        }
        accum_norm(av, bv);
        store_quarter(av[0], av[1], bv[0], bv[1], 2);
        store_quarter(av[2], av[3], bv[2], bv[3], 3);
        __syncthreads();

        if (c < 7) {
#pragma unroll
            for (int q = 0; q < 4; q++) {
                av[q] = ((const float4*)(Ag + (c + 1) * 64))[q];
                bv[q] = ((const float4*)(Bg + (c + 1) * 64))[q];
            }
            accum_norm(av, bv);
        }

#pragma unroll
        for (int ks = 0; ks < 4; ks++) {
            uint32_t afr[4][4], bfr[2][4];
#pragma unroll
            for (int mi = 0; mi < 4; mi++) {
                uint32_t addr = sAb + SWZ128((uint32_t)(a_mrow_base + mi * 16) * 128
                                             + (uint32_t)(ks * 32 + a_kb_base));
                ldmatrix_x4(afr[mi][0], afr[mi][1], afr[mi][2], afr[mi][3], addr);
            }
#pragma unroll
            for (int np = 0; np < 2; np++) {
                uint32_t addr = sBb + SWZ128((uint32_t)(b_nrow_base + np * 16) * 128
                                             + (uint32_t)(ks * 32 + b_kb_base));
                ldmatrix_x4(bfr[np][0], bfr[np][1], bfr[np][2], bfr[np][3], addr);
            }
#pragma unroll
            for (int mi = 0; mi < 4; mi++)
#pragma unroll
                for (int ni = 0; ni < 4; ni++)
                    mma_bf16(acc[mi][ni], afr[mi], &bfr[ni >> 1][(ni & 1) * 2]);
        }
        __syncthreads();
    }

    s_pna[lrow][half] = na_part;
    s_pnb[lrow][half] = nb_part;
    __syncthreads();

    const int g  = lane >> 2;
    const int cp = (lane & 3) * 2;
#pragma unroll
    for (int mi = 0; mi < 4; mi++) {
#pragma unroll
        for (int half_m = 0; half_m < 2; half_m++) {
            int mrow = moff + mi * 16 + half_m * 8 + g;
            float na = s_pna[mrow][0] + s_pna[mrow][1];
            float* grow = &g_cost[b][i0 + mrow][j0];
#pragma unroll
            for (int ni = 0; ni < 4; ni++) {
                int ncol = noff + ni * 8 + cp;
                float nb0 = s_pnb[ncol][0]     + s_pnb[ncol][1];
                float nb1 = s_pnb[ncol + 1][0] + s_pnb[ncol + 1][1];
                float d0 = acc[mi][ni][half_m * 2 + 0];
                float d1 = acc[mi][ni][half_m * 2 + 1];
                float2 o;
                o.x = sqrtf(fmaxf(na + nb0 - 2.f * d0, 0.f));
                o.y = sqrtf(fmaxf(na + nb1 - 2.f * d1, 0.f));
                *(float2*)(grow + ncol) = o;
            }
        }
    }
}

// ---------------------------------------------------------------------------
// Stage 2: DTW warp pipeline, SOFTWARE-PIPELINED: next step's cost loads are
// issued before this step's compute (L2 latency hidden under the DP chain).
// Chunk = 4 rows/step, 127 steps. Lane l owns cols [12l,12l+12).
// ---------------------------------------------------------------------------
#define CH 4
#define NCH (TT / CH)          // 96 row-chunks
#define NSTEPS (NCH + 31)      // 127

__global__ __launch_bounds__(32) void dtw_kernel() {
    const int b = blockIdx.x;
    const int lane = threadIdx.x;
    const float INF = __int_as_float(0x7f800000);
    const float* __restrict__ cb = &g_cost[b][0][0];

    float t[12], right[CH], cornerSave = INF;
#pragma unroll
    for (int j = 0; j < 12; j++) t[j] = INF;
#pragma unroll
    for (int i = 0; i < CH; i++) right[i] = INF;

    float4 cur[CH][3], nxt[CH][3];

    // preload step 0 (only lane 0 has a valid row chunk: r = -lane)
    {
        int r0 = 0 - lane;
        if (r0 >= 0 && r0 < NCH) {
            const float* rp = cb + (size_t)r0 * CH * TT + lane * 12;
#pragma unroll
            for (int ii = 0; ii < CH; ii++) {
                const float4* p4 = (const float4*)(rp + (size_t)ii * TT);
#pragma unroll
                for (int q = 0; q < 3; q++) cur[ii][q] = p4[q];
            }
        }
    }

    for (int s = 0; s < NSTEPS; s++) {
        // 1) prefetch step s+1 (independent loads, issued before the chain)
        int rn = s + 1 - lane;
        if (rn >= 0 && rn < NCH) {
            const float* rp = cb + (size_t)rn * CH * TT + lane * 12;
#pragma unroll
            for (int ii = 0; ii < CH; ii++) {
                const float4* p4 = (const float4*)(rp + (size_t)ii * TT);
#pragma unroll
                for (int q = 0; q < 3; q++) nxt[ii][q] = p4[q];
            }
        }

        // 2) neighbor handoff
        float lv[CH];
#pragma unroll
        for (int i = 0; i < CH; i++) lv[i] = __shfl_up_sync(0xffffffffu, right[i], 1);
        float cornerIn = __shfl_up_sync(0xffffffffu, cornerSave, 1);
        cornerSave = right[CH - 1];
        int r = s - lane;
        if (lane == 0) {
#pragma unroll
            for (int i = 0; i < CH; i++) lv[i] = INF;
            cornerIn = (r == 0) ? 0.f : INF;
        }

        // 3) compute step s from cur
        if (r >= 0 && r < NCH) {
#pragma unroll
            for (int ii = 0; ii < CH; ii++) {
                float cst[12] = {cur[ii][0].x, cur[ii][0].y, cur[ii][0].z, cur[ii][0].w,
                                 cur[ii][1].x, cur[ii][1].y, cur[ii][1].z, cur[ii][1].w,
                                 cur[ii][2].x, cur[ii][2].y, cur[ii][2].z, cur[ii][2].w};
                float m[12];
                m[0] = fminf(t[0], (ii == 0) ? cornerIn : lv[ii - 1]);
#pragma unroll
                for (int jj = 1; jj < 12; jj++) m[jj] = fminf(t[jj], t[jj - 1]);
                float cl = lv[ii];
#pragma unroll
                for (int jj = 0; jj < 12; jj++) {
                    float v = cst[jj] + fminf(m[jj], cl);
                    t[jj] = v;
                    cl = v;
                }
                right[ii] = cl;
            }
        }

        // 4) rotate prefetch buffer
#pragma unroll
        for (int ii = 0; ii < CH; ii++)
#pragma unroll
            for (int q = 0; q < 3; q++) cur[ii][q] = nxt[ii][q];
    }
    if (lane == 31) g_dist[b] = right[CH - 1];
}

// ---------------------------------------------------------------------------
// Stage 3: mean — unchanged
// ---------------------------------------------------------------------------
__global__ void reduce_kernel(float* __restrict__ out) {
    int lane = threadIdx.x;
    float s = g_dist[lane] + g_dist[lane + 32];
#pragma unroll
    for (int o = 16; o > 0; o >>= 1) s += __shfl_xor_sync(0xffffffffu, s, o);
    if (lane == 0) out[0] = s * (1.f / BB);
}

// ---------------------------------------------------------------------------
extern "C" void kernel_launch(void* const* d_in, const int* in_sizes, int n_in,
                              void* d_out, int out_size) {
    const float* pred = (const float*)d_in[0];
    const float* targ = (const float*)d_in[1];
    float* out = (float*)d_out;

    cost_hmma_kernel<<<dim3(TT / 128, TT / 128, BB), 256>>>(pred, targ);
    dtw_kernel<<<BB, 32>>>();
    reduce_kernel<<<1, 32>>>(out);
}

// round 12
// speedup vs baseline: 2.1778x; 1.0109x over previous
#include <cuda_runtime.h>
#include <cuda_bf16.h>
#include <math.h>
#include <cstdint>

#define BB 64
#define TT 384
#define DD 512

// ---------------------------------------------------------------------------
// Device scratch (no allocation allowed anywhere)
// ---------------------------------------------------------------------------
__device__ float g_cost[BB][TT][TT];   // ROW-major cost matrix
__device__ float g_dist[BB];

__device__ __forceinline__ uint32_t smem_u32(const void* p) {
    uint32_t a;
    asm("{ .reg .u64 t; cvta.to.shared.u64 t, %1; cvt.u32.u64 %0, t; }" : "=r"(a) : "l"(p));
    return a;
}
__device__ __forceinline__ uint32_t pack_bf16(float x, float y) {
    __nv_bfloat162 h = __floats2bfloat162_rn(x, y);
    return *reinterpret_cast<uint32_t*>(&h);
}
// SW64 swizzle for 64-byte rows: rotates 16B slot (bits[5:4]) by row bits[8:7]
#define SWZ64(off) ((off) ^ (((off) >> 3) & 0x30))

__device__ __forceinline__ void ldmatrix_x4(uint32_t& r0, uint32_t& r1,
                                            uint32_t& r2, uint32_t& r3, uint32_t addr) {
    asm volatile("ldmatrix.sync.aligned.m8n8.x4.shared.b16 {%0,%1,%2,%3}, [%4];"
                 : "=r"(r0), "=r"(r1), "=r"(r2), "=r"(r3) : "r"(addr));
}
__device__ __forceinline__ void mma_bf16(float* c, const uint32_t* a, const uint32_t* b) {
    asm volatile("mma.sync.aligned.m16n8k16.row.col.f32.bf16.bf16.f32 "
                 "{%0,%1,%2,%3}, {%4,%5,%6,%7}, {%8,%9}, {%0,%1,%2,%3};"
                 : "+f"(c[0]), "+f"(c[1]), "+f"(c[2]), "+f"(c[3])
                 : "r"(a[0]), "r"(a[1]), "r"(a[2]), "r"(a[3]), "r"(b[0]), "r"(b[1]));
}

// ---------------------------------------------------------------------------
// Stage 1: bf16 HMMA cost GEMM, BK=32, DOUBLE-BUFFERED smem: stores hit the
// idle buffer while MMAs consume the other; ONE barrier per chunk; next-chunk
// LDGs overlap MMAs. Norms fused into staging (R10-proven). 128x128 tile/CTA.
// ---------------------------------------------------------------------------
__global__ __launch_bounds__(256)
void cost_hmma_kernel(const float* __restrict__ pred, const float* __restrict__ targ) {
    __shared__ __align__(1024) unsigned char sA[2][128 * 64];  // 8KB per stage
    __shared__ __align__(1024) unsigned char sB[2][128 * 64];
    __shared__ float s_pna[128][2], s_pnb[128][2];

    const int b  = blockIdx.z;
    const int i0 = blockIdx.y * 128;
    const int j0 = blockIdx.x * 128;
    const int tid  = threadIdx.x;
    const int wid  = tid >> 5;
    const int lane = tid & 31;
    const int moff = (wid >> 2) * 64;   // warp m offset (0,64)
    const int noff = (wid & 3) * 32;    // warp n offset (0,32,64,96)

    // global->smem mapping: thread -> (row = tid>>1, 16-float half = tid&1)
    const int lrow = tid >> 1;
    const int half = tid & 1;
    const float* Ag = pred + (size_t)b * TT * DD + (size_t)(i0 + lrow) * DD + half * 16;
    const float* Bg = targ + (size_t)b * TT * DD + (size_t)(j0 + lrow) * DD + half * 16;
    const uint32_t dst = (uint32_t)lrow * 64 + half * 32;   // byte offset in stage

    // ldmatrix lane-address components
    const int quad = lane >> 3;
    const int r8   = lane & 7;
    const int a_mrow_base = moff + (quad & 1) * 8 + r8;
    const int a_kb_base   = (quad >> 1) * 16;          // byte col within 64B row
    const int b_nrow_base = noff + (quad >> 1) * 8 + r8;
    const int b_kb_base   = (quad & 1) * 16;

    float acc[4][4][4];
#pragma unroll
    for (int mi = 0; mi < 4; mi++)
#pragma unroll
        for (int ni = 0; ni < 4; ni++)
#pragma unroll
            for (int r = 0; r < 4; r++) acc[mi][ni][r] = 0.f;

    float na_part = 0.f, nb_part = 0.f;   // fused norm partials (16 floats/chunk)

    float4 av[4], bv[4];
#pragma unroll
    for (int q = 0; q < 4; q++) {
        av[q] = ((const float4*)Ag)[q];
        bv[q] = ((const float4*)Bg)[q];
        na_part += av[q].x * av[q].x + av[q].y * av[q].y + av[q].z * av[q].z + av[q].w * av[q].w;
        nb_part += bv[q].x * bv[q].x + bv[q].y * bv[q].y + bv[q].z * bv[q].z + bv[q].w * bv[q].w;
    }

    for (int c = 0; c < 16; c++) {       // 16 chunks of BK=32
        const int buf = c & 1;
        // staged chunk -> smem[buf] (fp32->bf16 fused, SW64 swizzle)
        {
            uint4 pa, pb;
            pa.x = pack_bf16(av[0].x, av[0].y); pa.y = pack_bf16(av[0].z, av[0].w);
            pa.z = pack_bf16(av[1].x, av[1].y); pa.w = pack_bf16(av[1].z, av[1].w);
            pb.x = pack_bf16(bv[0].x, bv[0].y); pb.y = pack_bf16(bv[0].z, bv[0].w);
            pb.z = pack_bf16(bv[1].x, bv[1].y); pb.w = pack_bf16(bv[1].z, bv[1].w);
            uint32_t o = SWZ64(dst);
            *(uint4*)(sA[buf] + o) = pa;
            *(uint4*)(sB[buf] + o) = pb;
            pa.x = pack_bf16(av[2].x, av[2].y); pa.y = pack_bf16(av[2].z, av[2].w);
            pa.z = pack_bf16(av[3].x, av[3].y); pa.w = pack_bf16(av[3].z, av[3].w);
            pb.x = pack_bf16(bv[2].x, bv[2].y); pb.y = pack_bf16(bv[2].z, bv[2].w);
            pb.z = pack_bf16(bv[3].x, bv[3].y); pb.w = pack_bf16(bv[3].z, bv[3].w);
            o = SWZ64(dst + 16);
            *(uint4*)(sA[buf] + o) = pa;
            *(uint4*)(sB[buf] + o) = pb;
        }
        __syncthreads();                 // smem[buf] ready; prior MMAs on it done

        if (c < 15) {                    // next-chunk LDGs overlap the MMAs below
            const float4* a4 = (const float4*)(Ag + (c + 1) * 32);
            const float4* b4 = (const float4*)(Bg + (c + 1) * 32);
#pragma unroll
            for (int q = 0; q < 4; q++) {
                av[q] = a4[q]; bv[q] = b4[q];
                na_part += av[q].x * av[q].x + av[q].y * av[q].y + av[q].z * av[q].z + av[q].w * av[q].w;
                nb_part += bv[q].x * bv[q].x + bv[q].y * bv[q].y + bv[q].z * bv[q].z + bv[q].w * bv[q].w;
            }
        }

        const uint32_t sAb = smem_u32(sA[buf]);
        const uint32_t sBb = smem_u32(sB[buf]);
#pragma unroll
        for (int ks = 0; ks < 2; ks++) { // 2 k-steps of 16 per chunk
            uint32_t afr[4][4], bfr[2][4];
#pragma unroll
            for (int mi = 0; mi < 4; mi++) {
                uint32_t addr = sAb + SWZ64((uint32_t)(a_mrow_base + mi * 16) * 64
                                            + (uint32_t)(ks * 32 + a_kb_base));
                ldmatrix_x4(afr[mi][0], afr[mi][1], afr[mi][2], afr[mi][3], addr);
            }
#pragma unroll
            for (int np = 0; np < 2; np++) {
                uint32_t addr = sBb + SWZ64((uint32_t)(b_nrow_base + np * 16) * 64
                                            + (uint32_t)(ks * 32 + b_kb_base));
                ldmatrix_x4(bfr[np][0], bfr[np][1], bfr[np][2], bfr[np][3], addr);
            }
#pragma unroll
            for (int mi = 0; mi < 4; mi++)
#pragma unroll
                for (int ni = 0; ni < 4; ni++)
                    mma_bf16(acc[mi][ni], afr[mi], &bfr[ni >> 1][(ni & 1) * 2]);
        }
    }

    // publish norm partials (each thread staged exactly half of its row)
    s_pna[lrow][half] = na_part;
    s_pnb[lrow][half] = nb_part;
    __syncthreads();

    // epilogue: cost = sqrt(max(na + nb - 2*dot, 0))
    const int g  = lane >> 2;
    const int cp = (lane & 3) * 2;
#pragma unroll
    for (int mi = 0; mi < 4; mi++) {
#pragma unroll
        for (int half_m = 0; half_m < 2; half_m++) {
            int mrow = moff + mi * 16 + half_m * 8 + g;
            float na = s_pna[mrow][0] + s_pna[mrow][1];
            float* grow = &g_cost[b][i0 + mrow][j0];
#pragma unroll
            for (int ni = 0; ni < 4; ni++) {
                int ncol = noff + ni * 8 + cp;
                float nb0 = s_pnb[ncol][0]     + s_pnb[ncol][1];
                float nb1 = s_pnb[ncol + 1][0] + s_pnb[ncol + 1][1];
                float d0 = acc[mi][ni][half_m * 2 + 0];
                float d1 = acc[mi][ni][half_m * 2 + 1];
                float2 o;
                o.x = sqrtf(fmaxf(na + nb0 - 2.f * d0, 0.f));
                o.y = sqrtf(fmaxf(na + nb1 - 2.f * d1, 0.f));
                *(float2*)(grow + ncol) = o;
            }
        }
    }
}

// ---------------------------------------------------------------------------
// Stage 2: DTW warp pipeline, software-pipelined, CH=3 rows/step (prefetch
// buffers 72 regs instead of 96 -> no spills). 159 steps.
// ---------------------------------------------------------------------------
#define CH 3
#define NCH (TT / CH)          // 128 row-chunks
#define NSTEPS (NCH + 31)      // 159

__global__ __launch_bounds__(32) void dtw_kernel() {
    const int b = blockIdx.x;
    const int lane = threadIdx.x;
    const float INF = __int_as_float(0x7f800000);
    const float* __restrict__ cb = &g_cost[b][0][0];

    float t[12], right[CH], cornerSave = INF;
#pragma unroll
    for (int j = 0; j < 12; j++) t[j] = INF;
#pragma unroll
    for (int i = 0; i < CH; i++) right[i] = INF;

    float4 cur[CH][3], nxt[CH][3];

    // preload step 0 (only lane 0 has a valid row chunk)
    {
        int r0 = 0 - lane;
        if (r0 >= 0 && r0 < NCH) {
            const float* rp = cb + (size_t)r0 * CH * TT + lane * 12;
#pragma unroll
            for (int ii = 0; ii < CH; ii++) {
                const float4* p4 = (const float4*)(rp + (size_t)ii * TT);
#pragma unroll
                for (int q = 0; q < 3; q++) cur[ii][q] = p4[q];
            }
        }
    }

    for (int s = 0; s < NSTEPS; s++) {
        // 1) prefetch step s+1 (independent loads issued ahead of the chain)
        int rn = s + 1 - lane;
        if (rn >= 0 && rn < NCH) {
            const float* rp = cb + (size_t)rn * CH * TT + lane * 12;
#pragma unroll
            for (int ii = 0; ii < CH; ii++) {
                const float4* p4 = (const float4*)(rp + (size_t)ii * TT);
#pragma unroll
                for (int q = 0; q < 3; q++) nxt[ii][q] = p4[q];
            }
        }

        // 2) neighbor handoff
        float lv[CH];
#pragma unroll
        for (int i = 0; i < CH; i++) lv[i] = __shfl_up_sync(0xffffffffu, right[i], 1);
        float cornerIn = __shfl_up_sync(0xffffffffu, cornerSave, 1);
        cornerSave = right[CH - 1];
        int r = s - lane;
        if (lane == 0) {
#pragma unroll
            for (int i = 0; i < CH; i++) lv[i] = INF;
            cornerIn = (r == 0) ? 0.f : INF;
        }

        // 3) compute step s from cur
        if (r >= 0 && r < NCH) {
#pragma unroll
            for (int ii = 0; ii < CH; ii++) {
                float cst[12] = {cur[ii][0].x, cur[ii][0].y, cur[ii][0].z, cur[ii][0].w,
                                 cur[ii][1].x, cur[ii][1].y, cur[ii][1].z, cur[ii][1].w,
                                 cur[ii][2].x, cur[ii][2].y, cur[ii][2].z, cur[ii][2].w};
                float m[12];
                m[0] = fminf(t[0], (ii == 0) ? cornerIn : lv[ii - 1]);
#pragma unroll
                for (int jj = 1; jj < 12; jj++) m[jj] = fminf(t[jj], t[jj - 1]);
                float cl = lv[ii];
#pragma unroll
                for (int jj = 0; jj < 12; jj++) {
                    float v = cst[jj] + fminf(m[jj], cl);
                    t[jj] = v;
                    cl = v;
                }
                right[ii] = cl;
            }
        }

        // 4) rotate prefetch buffer
#pragma unroll
        for (int ii = 0; ii < CH; ii++)
#pragma unroll
            for (int q = 0; q < 3; q++) cur[ii][q] = nxt[ii][q];
    }
    if (lane == 31) g_dist[b] = right[CH - 1];
}

// ---------------------------------------------------------------------------
// Stage 3: mean — unchanged
// ---------------------------------------------------------------------------
__global__ void reduce_kernel(float* __restrict__ out) {
    int lane = threadIdx.x;
    float s = g_dist[lane] + g_dist[lane + 32];
#pragma unroll
    for (int o = 16; o > 0; o >>= 1) s += __shfl_xor_sync(0xffffffffu, s, o);
    if (lane == 0) out[0] = s * (1.f / BB);
}

// ---------------------------------------------------------------------------
extern "C" void kernel_launch(void* const* d_in, const int* in_sizes, int n_in,
                              void* d_out, int out_size) {
    const float* pred = (const float*)d_in[0];
    const float* targ = (const float*)d_in[1];
    float* out = (float*)d_out;

    cost_hmma_kernel<<<dim3(TT / 128, TT / 128, BB), 256>>>(pred, targ);
    dtw_kernel<<<BB, 32>>>();
    reduce_kernel<<<1, 32>>>(out);
}

// round 15
// speedup vs baseline: 2.3795x; 1.0926x over previous
#include <cuda_runtime.h>
#include <cuda_bf16.h>
#include <math.h>
#include <cstdint>

#define BB 64
#define TT 384
#define DD 512

// ---------------------------------------------------------------------------
// Device scratch (no allocation allowed anywhere)
// ---------------------------------------------------------------------------
__device__ float g_cost[BB][TT][TT];   // fp32 cost matrix (R12-proven layout)
__device__ float g_dist[BB];

__device__ __forceinline__ uint32_t smem_u32(const void* p) {
    uint32_t a;
    asm("{ .reg .u64 t; cvta.to.shared.u64 t, %1; cvt.u32.u64 %0, t; }" : "=r"(a) : "l"(p));
    return a;
}
__device__ __forceinline__ uint32_t pack_bf16(float x, float y) {
    __nv_bfloat162 h = __floats2bfloat162_rn(x, y);
    return *reinterpret_cast<uint32_t*>(&h);
}
// SW64 swizzle for 64-byte rows: rotates 16B slot (bits[5:4]) by row bits[8:7]
#define SWZ64(off) ((off) ^ (((off) >> 3) & 0x30))

__device__ __forceinline__ void ldmatrix_x4(uint32_t& r0, uint32_t& r1,
                                            uint32_t& r2, uint32_t& r3, uint32_t addr) {
    asm volatile("ldmatrix.sync.aligned.m8n8.x4.shared.b16 {%0,%1,%2,%3}, [%4];"
                 : "=r"(r0), "=r"(r1), "=r"(r2), "=r"(r3) : "r"(addr));
}
__device__ __forceinline__ void mma_bf16(float* c, const uint32_t* a, const uint32_t* b) {
    asm volatile("mma.sync.aligned.m16n8k16.row.col.f32.bf16.bf16.f32 "
                 "{%0,%1,%2,%3}, {%4,%5,%6,%7}, {%8,%9}, {%0,%1,%2,%3};"
                 : "+f"(c[0]), "+f"(c[1]), "+f"(c[2]), "+f"(c[3])
                 : "r"(a[0]), "r"(a[1]), "r"(a[2]), "r"(a[3]), "r"(b[0]), "r"(b[1]));
}

// ---------------------------------------------------------------------------
// Stage 1: bf16 HMMA cost GEMM, BK=32, double-buffered smem (R12-proven:
// passed at 116.6us). Single new delta: both k-steps' fragments preloaded
// (12 back-to-back ldmatrix, then 32 dense MMAs). fp32 epilogue (R12-proven).
// ---------------------------------------------------------------------------
__global__ __launch_bounds__(256)
void cost_hmma_kernel(const float* __restrict__ pred, const float* __restrict__ targ) {
    __shared__ __align__(1024) unsigned char sA[2][128 * 64];
    __shared__ __align__(1024) unsigned char sB[2][128 * 64];
    __shared__ float s_pna[128][2], s_pnb[128][2];

    const int b  = blockIdx.z;
    const int i0 = blockIdx.y * 128;
    const int j0 = blockIdx.x * 128;
    const int tid  = threadIdx.x;
    const int wid  = tid >> 5;
    const int lane = tid & 31;
    const int moff = (wid >> 2) * 64;
    const int noff = (wid & 3) * 32;

    const int lrow = tid >> 1;
    const int half = tid & 1;
    const float* Ag = pred + (size_t)b * TT * DD + (size_t)(i0 + lrow) * DD + half * 16;
    const float* Bg = targ + (size_t)b * TT * DD + (size_t)(j0 + lrow) * DD + half * 16;
    const uint32_t dst = (uint32_t)lrow * 64 + half * 32;

    const int quad = lane >> 3;
    const int r8   = lane & 7;
    const int a_mrow_base = moff + (quad & 1) * 8 + r8;
    const int a_kb_base   = (quad >> 1) * 16;
    const int b_nrow_base = noff + (quad >> 1) * 8 + r8;
    const int b_kb_base   = (quad & 1) * 16;

    float acc[4][4][4];
#pragma unroll
    for (int mi = 0; mi < 4; mi++)
#pragma unroll
        for (int ni = 0; ni < 4; ni++)
#pragma unroll
            for (int r = 0; r < 4; r++) acc[mi][ni][r] = 0.f;

    float na_part = 0.f, nb_part = 0.f;

    float4 av[4], bv[4];
#pragma unroll
    for (int q = 0; q < 4; q++) {
        av[q] = ((const float4*)Ag)[q];
        bv[q] = ((const float4*)Bg)[q];
        na_part += av[q].x * av[q].x + av[q].y * av[q].y + av[q].z * av[q].z + av[q].w * av[q].w;
        nb_part += bv[q].x * bv[q].x + bv[q].y * bv[q].y + bv[q].z * bv[q].z + bv[q].w * bv[q].w;
    }

    for (int c = 0; c < 16; c++) {
        const int buf = c & 1;
        {
            uint4 pa, pb;
            pa.x = pack_bf16(av[0].x, av[0].y); pa.y = pack_bf16(av[0].z, av[0].w);
            pa.z = pack_bf16(av[1].x, av[1].y); pa.w = pack_bf16(av[1].z, av[1].w);
            pb.x = pack_bf16(bv[0].x, bv[0].y); pb.y = pack_bf16(bv[0].z, bv[0].w);
            pb.z = pack_bf16(bv[1].x, bv[1].y); pb.w = pack_bf16(bv[1].z, bv[1].w);
            uint32_t o = SWZ64(dst);
            *(uint4*)(sA[buf] + o) = pa;
            *(uint4*)(sB[buf] + o) = pb;
            pa.x = pack_bf16(av[2].x, av[2].y); pa.y = pack_bf16(av[2].z, av[2].w);
            pa.z = pack_bf16(av[3].x, av[3].y); pa.w = pack_bf16(av[3].z, av[3].w);
            pb.x = pack_bf16(bv[2].x, bv[2].y); pb.y = pack_bf16(bv[2].z, bv[2].w);
            pb.z = pack_bf16(bv[3].x, bv[3].y); pb.w = pack_bf16(bv[3].z, bv[3].w);
            o = SWZ64(dst + 16);
            *(uint4*)(sA[buf] + o) = pa;
            *(uint4*)(sB[buf] + o) = pb;
        }
        __syncthreads();

        if (c < 15) {
            const float4* a4 = (const float4*)(Ag + (c + 1) * 32);
            const float4* b4 = (const float4*)(Bg + (c + 1) * 32);
#pragma unroll
            for (int q = 0; q < 4; q++) {
                av[q] = a4[q]; bv[q] = b4[q];
                na_part += av[q].x * av[q].x + av[q].y * av[q].y + av[q].z * av[q].z + av[q].w * av[q].w;
                nb_part += bv[q].x * bv[q].x + bv[q].y * bv[q].y + bv[q].z * bv[q].z + bv[q].w * bv[q].w;
            }
        }

        const uint32_t sAb = smem_u32(sA[buf]);
        const uint32_t sBb = smem_u32(sB[buf]);
        // preload BOTH k-steps' fragments (12 independent ldmatrix), then 32 MMAs
        uint32_t afr[2][4][4], bfr[2][2][4];
#pragma unroll
        for (int ks = 0; ks < 2; ks++) {
#pragma unroll
            for (int mi = 0; mi < 4; mi++) {
                uint32_t addr = sAb + SWZ64((uint32_t)(a_mrow_base + mi * 16) * 64
                                            + (uint32_t)(ks * 32 + a_kb_base));
                ldmatrix_x4(afr[ks][mi][0], afr[ks][mi][1], afr[ks][mi][2], afr[ks][mi][3], addr);
            }
#pragma unroll
            for (int np = 0; np < 2; np++) {
                uint32_t addr = sBb + SWZ64((uint32_t)(b_nrow_base + np * 16) * 64
                                            + (uint32_t)(ks * 32 + b_kb_base));
                ldmatrix_x4(bfr[ks][np][0], bfr[ks][np][1], bfr[ks][np][2], bfr[ks][np][3], addr);
            }
        }
#pragma unroll
        for (int ks = 0; ks < 2; ks++)
#pragma unroll
            for (int mi = 0; mi < 4; mi++)
#pragma unroll
                for (int ni = 0; ni < 4; ni++)
                    mma_bf16(acc[mi][ni], afr[ks][mi], &bfr[ks][ni >> 1][(ni & 1) * 2]);
    }

    s_pna[lrow][half] = na_part;
    s_pnb[lrow][half] = nb_part;
    __syncthreads();

    // epilogue: fp32 cost stores (R12-proven)
    const int g  = lane >> 2;
    const int cp = (lane & 3) * 2;
#pragma unroll
    for (int mi = 0; mi < 4; mi++) {
#pragma unroll
        for (int half_m = 0; half_m < 2; half_m++) {
            int mrow = moff + mi * 16 + half_m * 8 + g;
            float na = s_pna[mrow][0] + s_pna[mrow][1];
            float* grow = &g_cost[b][i0 + mrow][j0];
#pragma unroll
            for (int ni = 0; ni < 4; ni++) {
                int ncol = noff + ni * 8 + cp;
                float nb0 = s_pnb[ncol][0]     + s_pnb[ncol][1];
                float nb1 = s_pnb[ncol + 1][0] + s_pnb[ncol + 1][1];
                float d0 = acc[mi][ni][half_m * 2 + 0];
                float d1 = acc[mi][ni][half_m * 2 + 1];
                float2 o;
                o.x = sqrtf(fmaxf(na + nb0 - 2.f * d0, 0.f));
                o.y = sqrtf(fmaxf(na + nb1 - 2.f * d1, 0.f));
                *(float2*)(grow + ncol) = o;
            }
        }
    }
}

// ---------------------------------------------------------------------------
// Stage 2: DTW warp pipeline — VERBATIM the R11 kernel (passed, ~99us):
// CH=4, software-pipelined fp32 prefetch, reassociated recurrence.
// ---------------------------------------------------------------------------
#define CH 4
#define NCH (TT / CH)          // 96 row-chunks
#define NSTEPS (NCH + 31)      // 127

__global__ __launch_bounds__(32) void dtw_kernel() {
    const int b = blockIdx.x;
    const int lane = threadIdx.x;
    const float INF = __int_as_float(0x7f800000);
    const float* __restrict__ cb = &g_cost[b][0][0];

    float t[12], right[CH], cornerSave = INF;
#pragma unroll
    for (int j = 0; j < 12; j++) t[j] = INF;
#pragma unroll
    for (int i = 0; i < CH; i++) right[i] = INF;

    float4 cur[CH][3], nxt[CH][3];

    // preload step 0 (only lane 0 has a valid row chunk)
    {
        int r0 = 0 - lane;
        if (r0 >= 0 && r0 < NCH) {
            const float* rp = cb + (size_t)r0 * CH * TT + lane * 12;
#pragma unroll
            for (int ii = 0; ii < CH; ii++) {
                const float4* p4 = (const float4*)(rp + (size_t)ii * TT);
#pragma unroll
                for (int q = 0; q < 3; q++) cur[ii][q] = p4[q];
            }
        }
    }

    for (int s = 0; s < NSTEPS; s++) {
        // 1) prefetch step s+1 (independent loads issued ahead of the chain)
        int rn = s + 1 - lane;
        if (rn >= 0 && rn < NCH) {
            const float* rp = cb + (size_t)rn * CH * TT + lane * 12;
#pragma unroll
            for (int ii = 0; ii < CH; ii++) {
                const float4* p4 = (const float4*)(rp + (size_t)ii * TT);
#pragma unroll
                for (int q = 0; q < 3; q++) nxt[ii][q] = p4[q];
            }
        }

        // 2) neighbor handoff
        float lv[CH];
#pragma unroll
        for (int i = 0; i < CH; i++) lv[i] = __shfl_up_sync(0xffffffffu, right[i], 1);
        float cornerIn = __shfl_up_sync(0xffffffffu, cornerSave, 1);
        cornerSave = right[CH - 1];
        int r = s - lane;
        if (lane == 0) {
#pragma unroll
            for (int i = 0; i < CH; i++) lv[i] = INF;
            cornerIn = (r == 0) ? 0.f : INF;
        }

        // 3) compute step s from cur
        if (r >= 0 && r < NCH) {
#pragma unroll
            for (int ii = 0; ii < CH; ii++) {
                float cst[12] = {cur[ii][0].x, cur[ii][0].y, cur[ii][0].z, cur[ii][0].w,
                                 cur[ii][1].x, cur[ii][1].y, cur[ii][1].z, cur[ii][1].w,
                                 cur[ii][2].x, cur[ii][2].y, cur[ii][2].z, cur[ii][2].w};
                float m[12];
                m[0] = fminf(t[0], (ii == 0) ? cornerIn : lv[ii - 1]);
#pragma unroll
                for (int jj = 1; jj < 12; jj++) m[jj] = fminf(t[jj], t[jj - 1]);
                float cl = lv[ii];
#pragma unroll
                for (int jj = 0; jj < 12; jj++) {
                    float v = cst[jj] + fminf(m[jj], cl);
                    t[jj] = v;
                    cl = v;
                }
                right[ii] = cl;
            }
        }

        // 4) rotate prefetch buffer
#pragma unroll
        for (int ii = 0; ii < CH; ii++)
#pragma unroll
            for (int q = 0; q < 3; q++) cur[ii][q] = nxt[ii][q];
    }
    if (lane == 31) g_dist[b] = right[CH - 1];
}

// ---------------------------------------------------------------------------
// Stage 3: mean — unchanged
// ---------------------------------------------------------------------------
__global__ void reduce_kernel(float* __restrict__ out) {
    int lane = threadIdx.x;
    float s = g_dist[lane] + g_dist[lane + 32];
#pragma unroll
    for (int o = 16; o > 0; o >>= 1) s += __shfl_xor_sync(0xffffffffu, s, o);
    if (lane == 0) out[0] = s * (1.f / BB);
}

// ---------------------------------------------------------------------------
extern "C" void kernel_launch(void* const* d_in, const int* in_sizes, int n_in,
                              void* d_out, int out_size) {
    const float* pred = (const float*)d_in[0];
    const float* targ = (const float*)d_in[1];
    float* out = (float*)d_out;

    cost_hmma_kernel<<<dim3(TT / 128, TT / 128, BB), 256>>>(pred, targ);
    dtw_kernel<<<BB, 32>>>();
    reduce_kernel<<<1, 32>>>(out);
}